// round 2
// baseline (speedup 1.0000x reference)
#include <cuda_runtime.h>
#include <math.h>

#define BB   2
#define HH   8
#define LL   4096
#define DMM  512
#define DHH  64
#define NBB  64
#define BSS  64
#define KPQ  9

__device__ float g_q[BB*HH*LL*DHH];
__device__ float g_k[BB*HH*LL*DHH];
__device__ float g_v[BB*HH*LL*DHH];
__device__ float g_qproj[BB*HH*NBB*DHH];
__device__ float g_kproj[BB*HH*NBB*DHH];
__device__ float g_pbias[HH*NBB*NBB];
__device__ int   g_sel[BB*HH*NBB*KPQ];
__device__ float g_sparse[BB*HH*LL*DHH];
__device__ float g_kv[BB*HH*DHH*DHH];
__device__ float g_ksum[BB*HH*DHH];
__device__ float g_blend[BB*LL*DMM];

#define FMA16(acc,a,b) { \
  acc[0][0]+=a.x*b.x; acc[0][1]+=a.x*b.y; acc[0][2]+=a.x*b.z; acc[0][3]+=a.x*b.w; \
  acc[1][0]+=a.y*b.x; acc[1][1]+=a.y*b.y; acc[1][2]+=a.y*b.z; acc[1][3]+=a.y*b.w; \
  acc[2][0]+=a.z*b.x; acc[2][1]+=a.z*b.y; acc[2][2]+=a.z*b.z; acc[2][3]+=a.z*b.w; \
  acc[3][0]+=a.w*b.x; acc[3][1]+=a.w*b.y; acc[3][2]+=a.w*b.z; acc[3][3]+=a.w*b.w; }

// C = X @ W^T ; mode 0: row-major out ; mode 1: BHLD layout
__global__ void gemm_xwt_kernel(const float* __restrict__ X, const float* __restrict__ W,
                                float* __restrict__ outp, int K, int mode) {
    __shared__ float Xs[16][68];
    __shared__ float Ws[16][68];
    int tid = threadIdx.x;
    int tx = tid & 15, ty = tid >> 4;
    int m0 = blockIdx.y << 6, n0 = blockIdx.x << 6;
    int lm = tid >> 2, lk = (tid & 3) << 2;
    float acc[4][4];
#pragma unroll
    for (int i = 0; i < 4; i++)
#pragma unroll
        for (int j = 0; j < 4; j++) acc[i][j] = 0.f;
    const float* Xp = X + (size_t)(m0 + lm) * K + lk;
    const float* Wp = W + (size_t)(n0 + lm) * K + lk;
    for (int k0 = 0; k0 < K; k0 += 16) {
        float4 xa = *(const float4*)(Xp + k0);
        float4 wa = *(const float4*)(Wp + k0);
        __syncthreads();
        Xs[lk+0][lm]=xa.x; Xs[lk+1][lm]=xa.y; Xs[lk+2][lm]=xa.z; Xs[lk+3][lm]=xa.w;
        Ws[lk+0][lm]=wa.x; Ws[lk+1][lm]=wa.y; Ws[lk+2][lm]=wa.z; Ws[lk+3][lm]=wa.w;
        __syncthreads();
#pragma unroll
        for (int kk = 0; kk < 16; kk++) {
            float4 a = *(const float4*)&Xs[kk][ty << 2];
            float4 b = *(const float4*)&Ws[kk][tx << 2];
            FMA16(acc, a, b);
        }
    }
    if (mode == 0) {
        int N = gridDim.x << 6;
#pragma unroll
        for (int ii = 0; ii < 4; ii++)
            *(float4*)&outp[(size_t)(m0 + (ty<<2) + ii) * N + n0 + (tx<<2)] =
                make_float4(acc[ii][0], acc[ii][1], acc[ii][2], acc[ii][3]);
    } else {
        int h = n0 >> 6;
#pragma unroll
        for (int ii = 0; ii < 4; ii++) {
            int m = m0 + (ty<<2) + ii;
            int b = m >> 12, l = m & 4095;
            *(float4*)&outp[(((size_t)(b*HH + h) * LL + l) << 6) + (tx<<2)] =
                make_float4(acc[ii][0], acc[ii][1], acc[ii][2], acc[ii][3]);
        }
    }
}

__global__ void pool_proj_kernel(const float* __restrict__ Wrq, const float* __restrict__ Wrk) {
    int qb = blockIdx.x, bh = blockIdx.y;
    int d = threadIdx.x;
    __shared__ float qp[DHH], kp[DHH];
    const float* qb_ = g_q + ((size_t)bh * LL + qb * BSS) * DHH;
    const float* kb_ = g_k + ((size_t)bh * LL + qb * BSS) * DHH;
    float sq = 0.f, sk = 0.f;
    for (int i = 0; i < BSS; i++) { sq += qb_[i*DHH + d]; sk += kb_[i*DHH + d]; }
    qp[d] = sq * (1.f / BSS);
    kp[d] = sk * (1.f / BSS);
    __syncthreads();
    float aq = 0.f, ak = 0.f;
    for (int e = 0; e < DHH; e++) { aq += qp[e] * Wrq[d*DHH + e]; ak += kp[e] * Wrk[d*DHH + e]; }
    g_qproj[((size_t)bh * NBB + qb) * DHH + d] = aq;
    g_kproj[((size_t)bh * NBB + qb) * DHH + d] = ak;
}

__global__ void pool_bias_kernel(const float* __restrict__ pb) {
    int h = blockIdx.y;
    int qb = blockIdx.x >> 6, kb = blockIdx.x & 63;
    const float* base = pb + ((size_t)h * LL + qb * BSS) * LL + kb * BSS;
    int t = threadIdx.x;
    int j = t & 63, i0 = t >> 6;
    float s = 0.f;
    for (int i = i0; i < BSS; i += 2) s += base[(size_t)i * LL + j];
    __shared__ float red[128];
    red[t] = s;
    __syncthreads();
    if (t < 64) red[t] += red[t + 64];
    __syncthreads();
    if (t < 32) {
        float v = red[t] + red[t + 32];
        for (int o = 16; o; o >>= 1) v += __shfl_xor_sync(0xffffffffu, v, o);
        if (t == 0) g_pbias[((size_t)h * NBB + qb) * NBB + kb] = v * (1.f / (BSS * BSS));
    }
}

__global__ void router_topk_kernel(const float* __restrict__ bscale_p) {
    __shared__ float sc[NBB][NBB];
    int bh = blockIdx.x;
    int h = bh & 7;
    float bsc = *bscale_p;
    const float* qp = g_qproj + (size_t)bh * NBB * DHH;
    const float* kp = g_kproj + (size_t)bh * NBB * DHH;
    for (int e = threadIdx.x; e < NBB * NBB; e += 256) {
        int qb = e >> 6, kb = e & 63;
        float s = 0.f;
        for (int d = 0; d < DHH; d++) s += qp[qb*DHH + d] * kp[kb*DHH + d];
        sc[qb][kb] = s * 0.125f + bsc * g_pbias[((size_t)h * NBB + qb) * NBB + kb];
    }
    __syncthreads();
    int warp = threadIdx.x >> 5, lane = threadIdx.x & 31;
    for (int r = warp; r < NBB; r += 8) {
        float v0 = sc[r][lane], v1 = sc[r][lane + 32];
        int i0 = lane, i1 = lane + 32;
        for (int t = 0; t < KPQ; t++) {
            float bv; int bi;
            if (v0 > v1 || (v0 == v1 && i0 < i1)) { bv = v0; bi = i0; }
            else { bv = v1; bi = i1; }
            for (int off = 16; off; off >>= 1) {
                float ov = __shfl_xor_sync(0xffffffffu, bv, off);
                int   oi = __shfl_xor_sync(0xffffffffu, bi, off);
                if (ov > bv || (ov == bv && oi < bi)) { bv = ov; bi = oi; }
            }
            if (lane == 0) g_sel[((size_t)bh * NBB + r) * KPQ + t] = bi;
            if (i0 == bi) v0 = -INFINITY;
            if (i1 == bi) v1 = -INFINITY;
        }
    }
}

__device__ __forceinline__ float fq_clip(float r) {
    return fminf(fmaxf(r, -128.f), 127.f);
}

// 256 threads: lrow=t>>2 row, lg=t&3 (16 cols each). Per-row symmetric fake-quant.
__device__ __forceinline__ void load_fq_block(const float* __restrict__ src_base,
                                              float* __restrict__ dst,
                                              int lrow, int lg, int transpose) {
    const float* src = src_base + (size_t)lrow * DHH + lg * 16;
    float x[16];
    float mx = 0.f;
#pragma unroll
    for (int c = 0; c < 16; c += 4) {
        float4 v = *(const float4*)(src + c);
        x[c] = v.x; x[c+1] = v.y; x[c+2] = v.z; x[c+3] = v.w;
    }
#pragma unroll
    for (int c = 0; c < 16; c++) mx = fmaxf(mx, fabsf(x[c]));
    mx = fmaxf(mx, __shfl_xor_sync(0xffffffffu, mx, 1));
    mx = fmaxf(mx, __shfl_xor_sync(0xffffffffu, mx, 2));
    float scale = fmaxf(mx, 1e-8f) / 127.0f;
    if (transpose) {
#pragma unroll
        for (int c = 0; c < 16; c++)
            dst[(lg*16 + c) * 68 + lrow] = fq_clip(rintf(x[c] / scale)) * scale;
    } else {
#pragma unroll
        for (int c = 0; c < 16; c += 4) {
            float4 o;
            o.x = fq_clip(rintf(x[c  ] / scale)) * scale;
            o.y = fq_clip(rintf(x[c+1] / scale)) * scale;
            o.z = fq_clip(rintf(x[c+2] / scale)) * scale;
            o.w = fq_clip(rintf(x[c+3] / scale)) * scale;
            *(float4*)&dst[lrow * 68 + lg*16 + c] = o;
        }
    }
}

#define SMEM_K5 ((576*68 + 64*68 + 64*68 + 192) * 4)

__global__ void sparse_attn_kernel(const float* __restrict__ pb) {
    extern __shared__ float sm[];
    float* ST   = sm;                  // [576][68] scores, transposed [j][i]
    float* qsT  = ST  + 576 * 68;      // [64][68]  fq(q)^T [d][i]
    float* kvb  = qsT + 64 * 68;       // [64][68]
    float* rowm = kvb + 64 * 68;
    float* rowz = rowm + 64;
    float* rowsc= rowz + 64;

    int qb = blockIdx.x, bh = blockIdx.y;
    int h = bh & 7;
    int t = threadIdx.x;
    int tx = t & 15, ty = t >> 4;
    int lrow = t >> 2, lg = t & 3;

    load_fq_block(g_q + ((size_t)bh * LL + qb * BSS) * DHH, qsT, lrow, lg, 1);
    __syncthreads();

    const int selbase = (bh * NBB + qb) * KPQ;
    int i0 = ty << 2, j0 = tx << 2;

    for (int kb = 0; kb < KPQ; kb++) {
        int kidx = g_sel[selbase + kb];
        load_fq_block(g_k + ((size_t)bh * LL + kidx * BSS) * DHH, kvb, lrow, lg, 1);
        __syncthreads();
        float acc[4][4];
#pragma unroll
        for (int i = 0; i < 4; i++)
#pragma unroll
            for (int j = 0; j < 4; j++) acc[i][j] = 0.f;
#pragma unroll 8
        for (int d = 0; d < 64; d++) {
            float4 a = *(const float4*)&qsT[d*68 + i0];
            float4 b = *(const float4*)&kvb[d*68 + j0];
            FMA16(acc, a, b);
        }
        const float* brow = pb + ((size_t)h * LL + qb * BSS + i0) * LL + (size_t)kidx * BSS + j0;
#pragma unroll
        for (int ii = 0; ii < 4; ii++) {
            float4 pv = *(const float4*)(brow + (size_t)ii * LL);
            acc[ii][0] += pv.x; acc[ii][1] += pv.y; acc[ii][2] += pv.z; acc[ii][3] += pv.w;
        }
#pragma unroll
        for (int jj = 0; jj < 4; jj++)
            *(float4*)&ST[(kb*64 + j0 + jj) * 68 + i0] =
                make_float4(acc[0][jj], acc[1][jj], acc[2][jj], acc[3][jj]);
        __syncthreads();
    }

    {
        float m = -INFINITY;
        for (int j = lg; j < 576; j += 4) m = fmaxf(m, ST[j*68 + lrow]);
        m = fmaxf(m, __shfl_xor_sync(0xffffffffu, m, 1));
        m = fmaxf(m, __shfl_xor_sync(0xffffffffu, m, 2));
        float z = 0.f;
        for (int j = lg; j < 576; j += 4) z += expf(ST[j*68 + lrow] - m);
        z += __shfl_xor_sync(0xffffffffu, z, 1);
        z += __shfl_xor_sync(0xffffffffu, z, 2);
        if (lg == 0) {
            rowm[lrow] = m; rowz[lrow] = z;
            rowsc[lrow] = fmaxf(1.0f / z, 1e-8f) / 127.0f;  // max weight = exp(0)/Z
        }
    }
    __syncthreads();

    for (int e = t; e < 576 * 64; e += 256) {
        int i = e & 63, j = e >> 6;
        float w = expf(ST[j*68 + i] - rowm[i]) / rowz[i];
        float sc = rowsc[i];
        ST[j*68 + i] = fq_clip(rintf(w / sc)) * sc;
    }
    __syncthreads();

    float acc2[4][4];
#pragma unroll
    for (int i = 0; i < 4; i++)
#pragma unroll
        for (int j = 0; j < 4; j++) acc2[i][j] = 0.f;
    for (int kb = 0; kb < KPQ; kb++) {
        int kidx = g_sel[selbase + kb];
        load_fq_block(g_v + ((size_t)bh * LL + kidx * BSS) * DHH, kvb, lrow, lg, 0);
        __syncthreads();
#pragma unroll 8
        for (int jl = 0; jl < 64; jl++) {
            float4 w  = *(const float4*)&ST[(kb*64 + jl) * 68 + i0];
            float4 vv = *(const float4*)&kvb[jl*68 + j0];
            FMA16(acc2, w, vv);
        }
        __syncthreads();
    }
    float* dst = g_sparse + ((size_t)bh * LL + qb * BSS) * DHH;
#pragma unroll
    for (int ii = 0; ii < 4; ii++)
        *(float4*)&dst[(i0 + ii) * DHH + j0] =
            make_float4(acc2[ii][0], acc2[ii][1], acc2[ii][2], acc2[ii][3]);
}

__global__ void linear_kv_kernel() {
    int bh = blockIdx.y;
    __shared__ float pk[64][68];
    __shared__ float vvs[64][68];
    __shared__ float ksred[64];
    int t = threadIdx.x;
    int tx = t & 15, ty = t >> 4;
    int lrow = t >> 2, lg = t & 3;
    float acc[4][4];
#pragma unroll
    for (int i = 0; i < 4; i++)
#pragma unroll
        for (int j = 0; j < 4; j++) acc[i][j] = 0.f;
    float ksp[16];
#pragma unroll
    for (int c = 0; c < 16; c++) ksp[c] = 0.f;
    if (t < 64) ksred[t] = 0.f;

    for (int sub = 0; sub < 4; sub++) {
        size_t l0 = (size_t)blockIdx.x * 256 + sub * 64;
        const float* ks = g_k + ((size_t)bh * LL + l0 + lrow) * DHH + lg * 16;
        const float* vs = g_v + ((size_t)bh * LL + l0 + lrow) * DHH + lg * 16;
        __syncthreads();
#pragma unroll
        for (int c = 0; c < 16; c += 4) {
            float4 kx = *(const float4*)(ks + c);
            float4 vx = *(const float4*)(vs + c);
            float p0 = kx.x > 0.f ? kx.x + 1.f : expm1f(kx.x) + 1.f;
            float p1 = kx.y > 0.f ? kx.y + 1.f : expm1f(kx.y) + 1.f;
            float p2 = kx.z > 0.f ? kx.z + 1.f : expm1f(kx.z) + 1.f;
            float p3 = kx.w > 0.f ? kx.w + 1.f : expm1f(kx.w) + 1.f;
            pk[lrow][lg*16 + c    ] = p0;
            pk[lrow][lg*16 + c + 1] = p1;
            pk[lrow][lg*16 + c + 2] = p2;
            pk[lrow][lg*16 + c + 3] = p3;
            ksp[c] += p0; ksp[c+1] += p1; ksp[c+2] += p2; ksp[c+3] += p3;
            *(float4*)&vvs[lrow][lg*16 + c] = vx;
        }
        __syncthreads();
#pragma unroll 8
        for (int l = 0; l < 64; l++) {
            float4 a = *(const float4*)&pk[l][ty << 2];
            float4 b = *(const float4*)&vvs[l][tx << 2];
            FMA16(acc, a, b);
        }
    }
    __syncthreads();
#pragma unroll
    for (int c = 0; c < 16; c++) atomicAdd(&ksred[lg*16 + c], ksp[c]);
    __syncthreads();
    float* kvo = g_kv + (size_t)bh * DHH * DHH;
#pragma unroll
    for (int di = 0; di < 4; di++)
#pragma unroll
        for (int mi = 0; mi < 4; mi++)
            atomicAdd(&kvo[((ty<<2) + di) * DHH + (tx<<2) + mi], acc[di][mi]);
    if (t < 64) atomicAdd(&g_ksum[(size_t)bh * DHH + t], ksred[t]);
}

__global__ void linear_out_blend_kernel(const float* __restrict__ alog) {
    int bh = blockIdx.y;
    int b = bh >> 3, h = bh & 7;
    __shared__ float kvs[64][64];
    __shared__ float kss[64];
    int t = threadIdx.x;
    for (int e = t; e < 4096; e += 256) kvs[e >> 6][e & 63] = g_kv[(size_t)bh * 4096 + e];
    if (t < 64) kss[t] = g_ksum[(size_t)bh * DHH + t];
    __syncthreads();
    float alpha = 1.f / (1.f + expf(-alog[h]));
    int warp = t >> 5, lane = t & 31;
    int l = blockIdx.x * 8 + warp;
    const float* qrow = g_q + ((size_t)bh * LL + l) * DHH;
    float x0 = qrow[lane], x1 = qrow[lane + 32];
    float p0 = x0 > 0.f ? x0 + 1.f : expm1f(x0) + 1.f;
    float p1 = x1 > 0.f ? x1 + 1.f : expm1f(x1) + 1.f;
    float den = p0 * kss[lane] + p1 * kss[lane + 32];
    for (int o = 16; o; o >>= 1) den += __shfl_xor_sync(0xffffffffu, den, o);
    float a0 = 0.f, a1 = 0.f;
#pragma unroll
    for (int d = 0; d < 64; d++) {
        float pv = (d < 32) ? __shfl_sync(0xffffffffu, p0, d)
                            : __shfl_sync(0xffffffffu, p1, d - 32);
        a0 += pv * kvs[d][lane];
        a1 += pv * kvs[d][lane + 32];
    }
    float dd = den + 1e-6f;
    const float* sp = g_sparse + ((size_t)bh * LL + l) * DHH;
    float* dst = g_blend + ((size_t)b * LL + l) * DMM + h * DHH;
    dst[lane]      = alpha * sp[lane]      + (1.f - alpha) * (a0 / dd);
    dst[lane + 32] = alpha * sp[lane + 32] + (1.f - alpha) * (a1 / dd);
}

extern "C" void kernel_launch(void* const* d_in, const int* in_sizes, int n_in,
                              void* d_out, int out_size) {
    const float* hs  = (const float*)d_in[0];
    const float* pb  = (const float*)d_in[1];
    const float* Wq  = (const float*)d_in[2];
    const float* Wk  = (const float*)d_in[3];
    const float* Wv  = (const float*)d_in[4];
    const float* Wo  = (const float*)d_in[5];
    const float* Wrq = (const float*)d_in[6];
    const float* Wrk = (const float*)d_in[7];
    const float* bsc = (const float*)d_in[8];
    const float* alo = (const float*)d_in[9];
    float* out = (float*)d_out;

    static int init_done = 0;
    if (!init_done) {
        cudaFuncSetAttribute(sparse_attn_kernel,
                             cudaFuncAttributeMaxDynamicSharedMemorySize, SMEM_K5);
        init_done = 1;
    }

    void *gq, *gk, *gv, *gbl, *gkv, *gks;
    cudaGetSymbolAddress(&gq,  g_q);
    cudaGetSymbolAddress(&gk,  g_k);
    cudaGetSymbolAddress(&gv,  g_v);
    cudaGetSymbolAddress(&gbl, g_blend);
    cudaGetSymbolAddress(&gkv, g_kv);
    cudaGetSymbolAddress(&gks, g_ksum);

    cudaMemsetAsync(gkv, 0, sizeof(float) * BB*HH*DHH*DHH);
    cudaMemsetAsync(gks, 0, sizeof(float) * BB*HH*DHH);

    dim3 gg(8, 128);
    gemm_xwt_kernel<<<gg, 256>>>(hs, Wq, (float*)gq, DMM, 1);
    gemm_xwt_kernel<<<gg, 256>>>(hs, Wk, (float*)gk, DMM, 1);
    gemm_xwt_kernel<<<gg, 256>>>(hs, Wv, (float*)gv, DMM, 1);

    pool_proj_kernel<<<dim3(NBB, BB*HH), DHH>>>(Wrq, Wrk);
    pool_bias_kernel<<<dim3(NBB*NBB, HH), 128>>>(pb);
    router_topk_kernel<<<BB*HH, 256>>>(bsc);

    sparse_attn_kernel<<<dim3(NBB, BB*HH), 256, SMEM_K5>>>(pb);

    linear_kv_kernel<<<dim3(LL/256, BB*HH), 256>>>();
    linear_out_blend_kernel<<<dim3(LL/8, BB*HH), 256>>>(alo);

    gemm_xwt_kernel<<<gg, 256>>>((const float*)gbl, Wo, out, DMM, 0);
}